// round 2
// baseline (speedup 1.0000x reference)
#include <cuda_runtime.h>
#include <cuda_bf16.h>

// Gather: out_means[b][d] = mean[d][labels[b][d]], out_log_vars[b][d] = log_var[d][labels[b][d]]
// B = 2097152, N_DOMAINS = 8, MAX_CONCEPTS = 64.
// d_out: [means B*8 floats][log_vars B*8 floats].
//
// Strategy: fused float2 smem table (mean, log_var interleaved) -> 8 LDS.64
// gathers/sample instead of 16 LDS.32; 2 samples/thread for ILP (4 front-
// batched LDG.128); streaming cache hints on the touch-once label/output
// streams.

#define N_DOMAINS 8
#define MAX_CONCEPTS 64
#define TAB (N_DOMAINS * MAX_CONCEPTS)   // 512 entries

__global__ __launch_bounds__(256, 8)
void concept_gauss_kernel(const int4* __restrict__ labels4,   // [B*2] int4
                          const float* __restrict__ mean,     // [512]
                          const float* __restrict__ log_var,  // [512]
                          float4* __restrict__ out4,          // [2B] means, [2B] log_vars
                          int B)
{
    __shared__ float2 s_tab[TAB];   // {mean, log_var} fused

    int t = threadIdx.x;
    s_tab[t]       = make_float2(mean[t],       log_var[t]);
    s_tab[t + 256] = make_float2(mean[t + 256], log_var[t + 256]);
    __syncthreads();

    // Two samples per thread, both coalesced within the block.
    int b0 = blockIdx.x * 512 + t;
    int b1 = b0 + 256;
    if (b1 >= B) {                    // tail guard (exact grid for B=2^21, but safe)
        if (b0 >= B) return;
        b1 = b0;                      // degenerate duplicate; writes idempotent
    }

    // Front-batched label loads: MLP_p1 = 4.
    int4 a0 = __ldcs(&labels4[2 * b0]);
    int4 a1 = __ldcs(&labels4[2 * b0 + 1]);
    int4 c0 = __ldcs(&labels4[2 * b1]);
    int4 c1 = __ldcs(&labels4[2 * b1 + 1]);

    // Sample 0 gathers (8x LDS.64)
    float2 g0 = s_tab[0 * MAX_CONCEPTS + a0.x];
    float2 g1 = s_tab[1 * MAX_CONCEPTS + a0.y];
    float2 g2 = s_tab[2 * MAX_CONCEPTS + a0.z];
    float2 g3 = s_tab[3 * MAX_CONCEPTS + a0.w];
    float2 g4 = s_tab[4 * MAX_CONCEPTS + a1.x];
    float2 g5 = s_tab[5 * MAX_CONCEPTS + a1.y];
    float2 g6 = s_tab[6 * MAX_CONCEPTS + a1.z];
    float2 g7 = s_tab[7 * MAX_CONCEPTS + a1.w];

    // Sample 1 gathers
    float2 h0 = s_tab[0 * MAX_CONCEPTS + c0.x];
    float2 h1 = s_tab[1 * MAX_CONCEPTS + c0.y];
    float2 h2 = s_tab[2 * MAX_CONCEPTS + c0.z];
    float2 h3 = s_tab[3 * MAX_CONCEPTS + c0.w];
    float2 h4 = s_tab[4 * MAX_CONCEPTS + c1.x];
    float2 h5 = s_tab[5 * MAX_CONCEPTS + c1.y];
    float2 h6 = s_tab[6 * MAX_CONCEPTS + c1.z];
    float2 h7 = s_tab[7 * MAX_CONCEPTS + c1.w];

    long vbase = 2L * B;   // log_vars offset in float4 units

    // Streaming 16B stores, fully coalesced.
    __stcs(&out4[2 * b0],             make_float4(g0.x, g1.x, g2.x, g3.x));
    __stcs(&out4[2 * b0 + 1],         make_float4(g4.x, g5.x, g6.x, g7.x));
    __stcs(&out4[2 * b1],             make_float4(h0.x, h1.x, h2.x, h3.x));
    __stcs(&out4[2 * b1 + 1],         make_float4(h4.x, h5.x, h6.x, h7.x));

    __stcs(&out4[vbase + 2 * b0],     make_float4(g0.y, g1.y, g2.y, g3.y));
    __stcs(&out4[vbase + 2 * b0 + 1], make_float4(g4.y, g5.y, g6.y, g7.y));
    __stcs(&out4[vbase + 2 * b1],     make_float4(h0.y, h1.y, h2.y, h3.y));
    __stcs(&out4[vbase + 2 * b1 + 1], make_float4(h4.y, h5.y, h6.y, h7.y));
}

extern "C" void kernel_launch(void* const* d_in, const int* in_sizes, int n_in,
                              void* d_out, int out_size) {
    const int4*  labels4 = (const int4*)d_in[0];
    const float* mean    = (const float*)d_in[1];
    const float* log_var = (const float*)d_in[2];
    float4* out4 = (float4*)d_out;

    int B = in_sizes[0] / N_DOMAINS;               // 2097152
    int blocks = (B + 511) / 512;                  // 512 samples per block
    concept_gauss_kernel<<<blocks, 256>>>(labels4, mean, log_var, out4, B);
}

// round 3
// speedup vs baseline: 1.2168x; 1.2168x over previous
#include <cuda_runtime.h>
#include <cuda_bf16.h>
#include <cstdint>

// out_means[b][d] = mean[d][labels[b][d]]; out_log_vars[b][d] = log_var[d][labels[b][d]]
// B = 2097152, N_DOMAINS = 8, MAX_CONCEPTS = 64.
// d_out: [means B*8 f32][log_vars B*8 f32].
//
// R3: scalar LDS.32 gathers (R1 layout — proven faster than float2), outputs
// staged in smem and flushed with 1D TMA bulk stores to remove STG.128 issue
// cost (12 cyc/instr) from the LSU pipe.

#define N_DOMAINS 8
#define MAX_CONCEPTS 64
#define TAB (N_DOMAINS * MAX_CONCEPTS)   // 512
#define BLK 256

__global__ __launch_bounds__(BLK, 8)
void concept_gauss_kernel(const int4* __restrict__ labels4,   // [B*2]
                          const float* __restrict__ mean,     // [512]
                          const float* __restrict__ log_var,  // [512]
                          float* __restrict__ out,            // [2*B*8]
                          int B)
{
    __shared__ float s_mean[TAB];
    __shared__ float s_var[TAB];
    __shared__ alignas(128) float st_mean[BLK * N_DOMAINS];  // 8 KB staging
    __shared__ alignas(128) float st_var[BLK * N_DOMAINS];   // 8 KB staging

    const int t = threadIdx.x;
    // Table load (2 KB each)
    s_mean[t]       = mean[t];
    s_mean[t + 256] = mean[t + 256];
    s_var[t]        = log_var[t];
    s_var[t + 256]  = log_var[t + 256];
    __syncthreads();

    const long base = (long)blockIdx.x * BLK;
    const long b    = base + t;
    const bool full_block = (base + BLK) <= (long)B;

    if (b < B) {
        // Front-batched label loads (MLP=2)
        int4 l0 = __ldcs(&labels4[2 * b]);
        int4 l1 = __ldcs(&labels4[2 * b + 1]);

        float m0 = s_mean[0 * MAX_CONCEPTS + l0.x];
        float m1 = s_mean[1 * MAX_CONCEPTS + l0.y];
        float m2 = s_mean[2 * MAX_CONCEPTS + l0.z];
        float m3 = s_mean[3 * MAX_CONCEPTS + l0.w];
        float m4 = s_mean[4 * MAX_CONCEPTS + l1.x];
        float m5 = s_mean[5 * MAX_CONCEPTS + l1.y];
        float m6 = s_mean[6 * MAX_CONCEPTS + l1.z];
        float m7 = s_mean[7 * MAX_CONCEPTS + l1.w];

        float v0 = s_var[0 * MAX_CONCEPTS + l0.x];
        float v1 = s_var[1 * MAX_CONCEPTS + l0.y];
        float v2 = s_var[2 * MAX_CONCEPTS + l0.z];
        float v3 = s_var[3 * MAX_CONCEPTS + l0.w];
        float v4 = s_var[4 * MAX_CONCEPTS + l1.x];
        float v5 = s_var[5 * MAX_CONCEPTS + l1.y];
        float v6 = s_var[6 * MAX_CONCEPTS + l1.z];
        float v7 = s_var[7 * MAX_CONCEPTS + l1.w];

        if (full_block) {
            // Stage in smem (STS.128 x4, crossbar-optimal 4 cyc each)
            float4* pm = reinterpret_cast<float4*>(&st_mean[t * N_DOMAINS]);
            float4* pv = reinterpret_cast<float4*>(&st_var[t * N_DOMAINS]);
            pm[0] = make_float4(m0, m1, m2, m3);
            pm[1] = make_float4(m4, m5, m6, m7);
            pv[0] = make_float4(v0, v1, v2, v3);
            pv[1] = make_float4(v4, v5, v6, v7);
        } else {
            // Tail fallback: direct stores
            float4* o = reinterpret_cast<float4*>(out);
            long vb = 2L * B;   // float4 units
            o[2 * b]          = make_float4(m0, m1, m2, m3);
            o[2 * b + 1]      = make_float4(m4, m5, m6, m7);
            o[vb + 2 * b]     = make_float4(v0, v1, v2, v3);
            o[vb + 2 * b + 1] = make_float4(v4, v5, v6, v7);
        }
    }

    if (!full_block) return;

    __syncthreads();

    if (t == 0) {
        // Order generic-proxy STS before async-proxy TMA reads.
        asm volatile("fence.proxy.async.shared::cta;" ::: "memory");

        uint32_t sm_mean, sm_var;
        asm("{ .reg .u64 a; cvta.to.shared.u64 a, %1; cvt.u32.u64 %0, a; }"
            : "=r"(sm_mean) : "l"(st_mean));
        asm("{ .reg .u64 a; cvta.to.shared.u64 a, %1; cvt.u32.u64 %0, a; }"
            : "=r"(sm_var) : "l"(st_var));

        const uint32_t bytes = BLK * N_DOMAINS * sizeof(float);  // 8192
        float* dst_mean = out + base * N_DOMAINS;
        float* dst_var  = out + (long)B * N_DOMAINS + base * N_DOMAINS;

        asm volatile(
            "cp.async.bulk.global.shared::cta.bulk_group [%0], [%1], %2;"
            :: "l"(dst_mean), "r"(sm_mean), "r"(bytes) : "memory");
        asm volatile(
            "cp.async.bulk.global.shared::cta.bulk_group [%0], [%1], %2;"
            :: "l"(dst_var), "r"(sm_var), "r"(bytes) : "memory");
        asm volatile("cp.async.bulk.commit_group;" ::: "memory");
        asm volatile("cp.async.bulk.wait_group 0;" ::: "memory");
    }
    // Keep smem alive until the bulk stores have drained.
    __syncthreads();
}

extern "C" void kernel_launch(void* const* d_in, const int* in_sizes, int n_in,
                              void* d_out, int out_size) {
    const int4*  labels4 = (const int4*)d_in[0];
    const float* mean    = (const float*)d_in[1];
    const float* log_var = (const float*)d_in[2];
    float* out = (float*)d_out;

    int B = in_sizes[0] / N_DOMAINS;   // 2097152
    int blocks = (B + BLK - 1) / BLK;  // 8192
    concept_gauss_kernel<<<blocks, BLK>>>(labels4, mean, log_var, out, B);
}